// round 3
// baseline (speedup 1.0000x reference)
#include <cuda_runtime.h>
#include <cstdint>

#define HB 768
#define N2 6144
#define D2 1536
#define RECB 128
#define RECT 384

// ----------------------------- scratch (device globals; allocation-free) ----
__device__ float g_pre [1024 * N2];
__device__ float g_seqA[1024 * D2];
__device__ float g_seqB[1024 * D2];
__device__ float g_hbuf[2 * 2 * 4 * HB];   // [parity][dir][b][HB]
__device__ float g_hq  [256 * HB];
__device__ float g_hk  [1024 * HB];
__device__ float g_P   [256 * 256];
__device__ float g_sf  [256 * D2];
__device__ float g_tmpT[256 * 2304];
__device__ float g_adv [256 * 3];
__device__ volatile unsigned g_gen;
__device__ unsigned g_cnt;

// ---------------------------------------------------------------------------
// SGEMM 128x128x16: C = A @ B^T (+bias). A:[M,K] rm lda, B:[N,K] rm ldb.
// 256 thr, 8x8 per thread. M,N multiples of 128, K multiple of 16.
// ---------------------------------------------------------------------------
__global__ __launch_bounds__(256, 2)
void sgemm128_abT(const float* __restrict__ A, int lda,
                  const float* __restrict__ B, int ldb,
                  const float* __restrict__ bias,
                  float* __restrict__ C, int ldc, int K)
{
    __shared__ float As[16][132];
    __shared__ float Bs[16][132];
    const int tid = threadIdx.x;
    const int m0 = blockIdx.y * 128, n0 = blockIdx.x * 128;
    const int tx = tid & 15, ty = tid >> 4;
    const int lrow = tid >> 2, lk = (tid & 3) * 4;

    float acc[8][8];
#pragma unroll
    for (int i = 0; i < 8; i++)
#pragma unroll
        for (int j = 0; j < 8; j++) acc[i][j] = 0.f;

    const float* Ap0 = A + (size_t)(m0 + lrow) * lda + lk;
    const float* Ap1 = A + (size_t)(m0 + 64 + lrow) * lda + lk;
    const float* Bp0 = B + (size_t)(n0 + lrow) * ldb + lk;
    const float* Bp1 = B + (size_t)(n0 + 64 + lrow) * ldb + lk;

    for (int k0 = 0; k0 < K; k0 += 16) {
        float4 a0 = *(const float4*)(Ap0 + k0);
        float4 a1 = *(const float4*)(Ap1 + k0);
        float4 b0 = *(const float4*)(Bp0 + k0);
        float4 b1 = *(const float4*)(Bp1 + k0);
        __syncthreads();
        As[lk+0][lrow]=a0.x; As[lk+1][lrow]=a0.y; As[lk+2][lrow]=a0.z; As[lk+3][lrow]=a0.w;
        As[lk+0][64+lrow]=a1.x; As[lk+1][64+lrow]=a1.y; As[lk+2][64+lrow]=a1.z; As[lk+3][64+lrow]=a1.w;
        Bs[lk+0][lrow]=b0.x; Bs[lk+1][lrow]=b0.y; Bs[lk+2][lrow]=b0.z; Bs[lk+3][lrow]=b0.w;
        Bs[lk+0][64+lrow]=b1.x; Bs[lk+1][64+lrow]=b1.y; Bs[lk+2][64+lrow]=b1.z; Bs[lk+3][64+lrow]=b1.w;
        __syncthreads();
#pragma unroll
        for (int kk = 0; kk < 16; kk++) {
            float ar[8], br[8];
            *(float4*)&ar[0] = *(const float4*)&As[kk][ty * 4];
            *(float4*)&ar[4] = *(const float4*)&As[kk][64 + ty * 4];
            *(float4*)&br[0] = *(const float4*)&Bs[kk][tx * 4];
            *(float4*)&br[4] = *(const float4*)&Bs[kk][64 + tx * 4];
#pragma unroll
            for (int i = 0; i < 8; i++)
#pragma unroll
                for (int j = 0; j < 8; j++) acc[i][j] += ar[i] * br[j];
        }
    }
    float bj[8];
#pragma unroll
    for (int j = 0; j < 8; j++) {
        int n = (j < 4) ? (n0 + tx * 4 + j) : (n0 + 64 + tx * 4 + j - 4);
        bj[j] = bias ? bias[n] : 0.f;
    }
#pragma unroll
    for (int i = 0; i < 8; i++) {
        int m = (i < 4) ? (m0 + ty * 4 + i) : (m0 + 64 + ty * 4 + i - 4);
        float4 v0 = make_float4(acc[i][0]+bj[0], acc[i][1]+bj[1], acc[i][2]+bj[2], acc[i][3]+bj[3]);
        float4 v1 = make_float4(acc[i][4]+bj[4], acc[i][5]+bj[5], acc[i][6]+bj[6], acc[i][7]+bj[7]);
        *(float4*)&C[(size_t)m * ldc + n0 + tx * 4] = v0;
        *(float4*)&C[(size_t)m * ldc + n0 + 64 + tx * 4] = v1;
    }
}

// ---------------------------------------------------------------------------
// Batched GEMM 64x64x16: C = A @ B (A:[M,K] rm, B:[K,N] rm). For P @ out.
// ---------------------------------------------------------------------------
__global__ __launch_bounds__(256)
void gemm_ab64(const float* __restrict__ Ab, int lda, size_t strA,
               const float* __restrict__ Bb, int ldb, size_t strB,
               float* __restrict__ Cb, int ldc, size_t strC, int K)
{
    const float* A = Ab + strA * blockIdx.z;
    const float* B = Bb + strB * blockIdx.z;
    float* C = Cb + strC * blockIdx.z;
    __shared__ float As[16][68];
    __shared__ float Bs[16][68];
    const int tid = threadIdx.x;
    const int m0 = blockIdx.y * 64, n0 = blockIdx.x * 64;
    const int tx = tid & 15, ty = tid >> 4;
    const int lrow = tid >> 2, lk = (tid & 3) * 4;
    const int bkk = tid >> 4, bnq = (tid & 15) * 4;

    float acc[4][4];
#pragma unroll
    for (int i = 0; i < 4; i++)
#pragma unroll
        for (int j = 0; j < 4; j++) acc[i][j] = 0.f;

    for (int k0 = 0; k0 < K; k0 += 16) {
        float4 a0 = *(const float4*)&A[(size_t)(m0 + lrow) * lda + k0 + lk];
        float4 b0 = *(const float4*)&B[(size_t)(k0 + bkk) * ldb + n0 + bnq];
        __syncthreads();
        As[lk+0][lrow]=a0.x; As[lk+1][lrow]=a0.y; As[lk+2][lrow]=a0.z; As[lk+3][lrow]=a0.w;
        *(float4*)&Bs[bkk][bnq] = b0;
        __syncthreads();
#pragma unroll
        for (int kk = 0; kk < 16; kk++) {
            float ar[4], br[4];
            *(float4*)&ar[0] = *(const float4*)&As[kk][ty * 4];
            *(float4*)&br[0] = *(const float4*)&Bs[kk][tx * 4];
#pragma unroll
            for (int i = 0; i < 4; i++)
#pragma unroll
                for (int j = 0; j < 4; j++) acc[i][j] += ar[i] * br[j];
        }
    }
#pragma unroll
    for (int i = 0; i < 4; i++) {
        float4 v = make_float4(acc[i][0], acc[i][1], acc[i][2], acc[i][3]);
        *(float4*)&C[(size_t)(m0 + ty * 4 + i) * ldc + n0 + tx * 4] = v;
    }
}

// ---------------------------------------------------------------------------
// Persistent BiLSTM recurrence. 128 CTAs x 384 thr. CTA: dir = bx>>6,
// cells [c0,c0+12), all 4 gates (48 Whh rows in SMEM). Grid barrier per step.
// ---------------------------------------------------------------------------
__device__ __forceinline__ float sigf(float x) { return 1.f / (1.f + expf(-x)); }

__global__ __launch_bounds__(RECT, 1)
void rec_kernel(const float* __restrict__ pre,   // [1024][6144]
                const float* __restrict__ whh,   // [2][3072][768]
                float* __restrict__ out,         // [1024][1536]
                int T)
{
    extern __shared__ float sm[];
    float* sW     = sm;               // [48][768]
    float* sh     = sW + 48 * 768;    // [4][768]
    float* sgates = sh + 4 * 768;     // [48][4]
    float* spre   = sgates + 192;     // [48][4]
    float* scst   = spre + 192;       // [48]  (12 cells x 4 b)
    __shared__ unsigned s_gen;

    const int tid = threadIdx.x;
    const int dir = blockIdx.x >> 6;
    const int c0  = (blockIdx.x & 63) * 12;
    const int rg  = tid >> 5, ks = tid & 31;

    // stage Whh slice: row r=g*12+jj <- whh[dir][g*768+c0+jj][:]
    for (int idx = tid; idx < 9216; idx += RECT) {
        int r = idx / 192, kc = (idx - r * 192) * 4;
        int g = r / 12, jj = r - g * 12;
        *(float4*)&sW[r * 768 + kc] =
            *(const float4*)&whh[((size_t)dir * 3072 + g * 768 + c0 + jj) * 768 + kc];
    }
    if (tid < 48) {
        scst[tid] = 0.f;
        int jj = tid >> 2, b = tid & 3;
        __stcg(&g_hbuf[((0 * 2 + dir) * 4 + b) * HB + c0 + jj], 0.f);
    }
    if (tid == 0) s_gen = g_gen;

#define GB() do { \
    __syncthreads(); \
    if (tid == 0) { \
        __threadfence(); \
        unsigned tgt = s_gen + 1; s_gen = tgt; \
        if (atomicAdd(&g_cnt, 1u) == RECB - 1u) { \
            atomicExch(&g_cnt, 0u); __threadfence(); g_gen = tgt; \
        } else { \
            while ((int)(g_gen - tgt) < 0) {} __threadfence(); \
        } \
    } \
    __syncthreads(); } while (0)

    GB();   // h zeros + s_gen visible

    int par = 0;
    for (int step = 0; step < T; step++) {
        const int t = (dir == 0) ? step : (T - 1 - step);

        // prefetch pre-activations (one per (row,b))
        float prev = 0.f;
        if (tid < 192) {
            int r = tid >> 2, b = tid & 3;
            int g = r / 12, jj = r - g * 12;
            prev = __ldg(&pre[(size_t)(b * 256 + t) * N2 + dir * 3072 + g * 768 + c0 + jj]);
        }
        // stage h from L2 (bypass L1: other SMs wrote it)
        for (int idx = tid; idx < 768; idx += RECT) {
            int b = idx / 192, kc = (idx - b * 192) * 4;
            *(float4*)&sh[b * 768 + kc] =
                __ldcg((const float4*)&g_hbuf[((par * 2 + dir) * 4 + b) * HB + kc]);
        }
        __syncthreads();

        // warp rg: rows rg*4..+3 x 4 batches, k split across lanes
        float acc[4][4];
#pragma unroll
        for (int i = 0; i < 4; i++)
#pragma unroll
            for (int b = 0; b < 4; b++) acc[i][b] = 0.f;
        const float* wb = sW + (rg * 4) * 768;
#pragma unroll
        for (int it = 0; it < 6; it++) {
            int ko = it * 128 + ks * 4;
            float4 w0 = *(const float4*)(wb + 0 * 768 + ko);
            float4 w1 = *(const float4*)(wb + 1 * 768 + ko);
            float4 w2 = *(const float4*)(wb + 2 * 768 + ko);
            float4 w3 = *(const float4*)(wb + 3 * 768 + ko);
            float4 h0 = *(const float4*)(sh + 0 * 768 + ko);
            float4 h1 = *(const float4*)(sh + 1 * 768 + ko);
            float4 h2 = *(const float4*)(sh + 2 * 768 + ko);
            float4 h3 = *(const float4*)(sh + 3 * 768 + ko);
#define FMA16(I, W) \
            acc[I][0] += W.x*h0.x + W.y*h0.y + W.z*h0.z + W.w*h0.w; \
            acc[I][1] += W.x*h1.x + W.y*h1.y + W.z*h1.z + W.w*h1.w; \
            acc[I][2] += W.x*h2.x + W.y*h2.y + W.z*h2.z + W.w*h2.w; \
            acc[I][3] += W.x*h3.x + W.y*h3.y + W.z*h3.z + W.w*h3.w;
            FMA16(0, w0) FMA16(1, w1) FMA16(2, w2) FMA16(3, w3)
#undef FMA16
        }
#pragma unroll
        for (int o = 16; o; o >>= 1)
#pragma unroll
            for (int i = 0; i < 4; i++)
#pragma unroll
                for (int b = 0; b < 4; b++)
                    acc[i][b] += __shfl_xor_sync(0xffffffffu, acc[i][b], o);
        if (ks == 0) {
#pragma unroll
            for (int i = 0; i < 4; i++)
#pragma unroll
                for (int b = 0; b < 4; b++)
                    sgates[(rg * 4 + i) * 4 + b] = acc[i][b];
        }
        if (tid < 192) spre[tid] = prev;
        __syncthreads();

        if (tid < 48) {
            int jj = tid >> 2, b = tid & 3;
            float xi = sgates[(0 * 12 + jj) * 4 + b] + spre[(0 * 12 + jj) * 4 + b];
            float xf = sgates[(1 * 12 + jj) * 4 + b] + spre[(1 * 12 + jj) * 4 + b];
            float xg = sgates[(2 * 12 + jj) * 4 + b] + spre[(2 * 12 + jj) * 4 + b];
            float xo = sgates[(3 * 12 + jj) * 4 + b] + spre[(3 * 12 + jj) * 4 + b];
            float c = sigf(xf) * scst[tid] + sigf(xi) * tanhf(xg);
            float h = sigf(xo) * tanhf(c);
            scst[tid] = c;
            int cell = c0 + jj;
            __stcg(&g_hbuf[(((par ^ 1) * 2 + dir) * 4 + b) * HB + cell], h);
            out[(size_t)(b * 256 + t) * D2 + dir * HB + cell] = h;
        }
        GB();
        par ^= 1;
    }
#undef GB
}

// ---------------------------------------------------------------------------
__global__ void tanh4_kernel(float* __restrict__ x, int n4)
{
    int i = blockIdx.x * blockDim.x + threadIdx.x;
    if (i < n4) {
        float4 v = ((float4*)x)[i];
        v.x = tanhf(v.x); v.y = tanhf(v.y); v.z = tanhf(v.z); v.w = tanhf(v.w);
        ((float4*)x)[i] = v;
    }
}

__device__ __forceinline__ float blockReduceSum(float v, float* sr)
{
    __syncthreads();
#pragma unroll
    for (int o = 16; o; o >>= 1) v += __shfl_xor_sync(0xffffffffu, v, o);
    int lane = threadIdx.x & 31, w = threadIdx.x >> 5;
    if (lane == 0) sr[w] = v;
    __syncthreads();
    if (w == 0) {
        int nw = (blockDim.x + 31) >> 5;
        v = (lane < nw) ? sr[lane] : 0.f;
#pragma unroll
        for (int o = 16; o; o >>= 1) v += __shfl_xor_sync(0xffffffffu, v, o);
        if (lane == 0) sr[0] = v;
    }
    __syncthreads();
    return sr[0];
}

// scores + softmax: block per (b,q); thread = k. P[bq][k] = softmax-ish.
__global__ __launch_bounds__(256)
void scores_kernel(const float* __restrict__ hq, const float* __restrict__ hk,
                   const float* __restrict__ w2, const float* __restrict__ b2p,
                   const float* __restrict__ am, const float* __restrict__ smk,
                   float* __restrict__ P)
{
    __shared__ float shq[768], sw2[768], shk[256 * 33], sr[32];
    const int tid = threadIdx.x, bq = blockIdx.x;
    const int b = bq >> 6, q = bq & 63;
    for (int i = tid; i < 768; i += 256) { shq[i] = hq[bq * 768 + i]; sw2[i] = w2[i]; }
    float acc = 0.f;
    for (int e0 = 0; e0 < 768; e0 += 32) {
        __syncthreads();
        for (int idx = tid; idx < 256 * 32; idx += 256) {
            int k = idx >> 5, e = idx & 31;
            shk[k * 33 + e] = hk[(size_t)((b << 8) + k) * 768 + e0 + e];
        }
        __syncthreads();
#pragma unroll 8
        for (int e = 0; e < 32; e++) {
            float v = shq[e0 + e] + shk[tid * 33 + e];
            acc += fmaxf(v, 0.f) * sw2[e0 + e];
        }
    }
    float score = acc + b2p[0];
    float m = am[b * 64 + q] * smk[b * 256 + tid];
    float a = (m == 0.f) ? 0.f : expf(score);
    float s = blockReduceSum(a, sr);
    P[bq * 256 + tid] = a / fmaxf(s, 2e-15f);
}

// adv[bq][l] = sum_h tmpT[bq][l*768+h] * actions[bq][h] + bias[l]
__global__ __launch_bounds__(256)
void adv_kernel(const float* __restrict__ tmpT, const float* __restrict__ act,
                const float* __restrict__ bias, float* __restrict__ adv)
{
    __shared__ float sa[768], sr[32];
    const int tid = threadIdx.x, bq = blockIdx.x;
    for (int i = tid; i < 768; i += 256) sa[i] = act[(size_t)bq * 768 + i];
    for (int l = 0; l < 3; l++) {
        float acc = 0.f;
        for (int h = tid; h < 768; h += 256)
            acc += tmpT[(size_t)bq * 2304 + l * 768 + h] * sa[h];
        float s = blockReduceSum(acc, sr);
        if (tid == 0) adv[bq * 3 + l] = s + bias[l];
    }
}

// final: val + adv - mean(adv); block per b
__global__ __launch_bounds__(256)
void final_kernel(const float* __restrict__ sf, const float* __restrict__ adv,
                  const float* __restrict__ valW, const float* __restrict__ valbp,
                  const float* __restrict__ am, float* __restrict__ out)
{
    __shared__ float sr[32];
    const int tid = threadIdx.x, b = blockIdx.x;
    float accv = 0.f;
    for (int d = tid; d < D2; d += 256) {
        float s = 0.f;
        for (int q = 0; q < 64; q++) s += sf[(size_t)(b * 64 + q) * D2 + d];
        accv += s * valW[d];
    }
    accv = blockReduceSum(accv, sr);
    float nv = (tid < 64) ? am[b * 64 + tid] : 0.f;
    nv = blockReduceSum(nv, sr);
    float asum = 0.f;
    for (int i = tid; i < 192; i += 256) asum += adv[b * 192 + i];
    asum = blockReduceSum(asum, sr);
    float val = accv / nv + valbp[0];
    float mean = asum / 192.f;
    for (int i = tid; i < 192; i += 256)
        out[b * 192 + i] = val + adv[b * 192 + i] - mean;
}

// ---------------------------------------------------------------------------
extern "C" void kernel_launch(void* const* d_in, const int* in_sizes, int n_in,
                              void* d_out, int out_size)
{
    const float* states  = (const float*)d_in[0];
    const float* smask   = (const float*)d_in[1];
    const float* actions = (const float*)d_in[2];
    const float* amask   = (const float*)d_in[3];
    const float* Wih0    = (const float*)d_in[4];
    const float* Whh0    = (const float*)d_in[5];
    const float* b0      = (const float*)d_in[6];
    const float* Wih12   = (const float*)d_in[7];
    const float* Whh12   = (const float*)d_in[8];
    const float* b12     = (const float*)d_in[9];
    const float* attnW1  = (const float*)d_in[10];
    const float* attnb1  = (const float*)d_in[11];
    const float* attnW2  = (const float*)d_in[12];
    const float* attnb2  = (const float*)d_in[13];
    const float* valW    = (const float*)d_in[14];
    const float* valb    = (const float*)d_in[15];
    const float* weight  = (const float*)d_in[16];
    const float* bias    = (const float*)d_in[17];
    float* out = (float*)d_out;

    float *pre, *seqA, *seqB, *hq, *hk, *P, *sf, *tmpT, *adv;
    cudaGetSymbolAddress((void**)&pre,  g_pre);
    cudaGetSymbolAddress((void**)&seqA, g_seqA);
    cudaGetSymbolAddress((void**)&seqB, g_seqB);
    cudaGetSymbolAddress((void**)&hq,   g_hq);
    cudaGetSymbolAddress((void**)&hk,   g_hk);
    cudaGetSymbolAddress((void**)&P,    g_P);
    cudaGetSymbolAddress((void**)&sf,   g_sf);
    cudaGetSymbolAddress((void**)&tmpT, g_tmpT);
    cudaGetSymbolAddress((void**)&adv,  g_adv);

    const int rec_smem = (48 * 768 + 4 * 768 + 192 + 192 + 48) * 4;
    cudaFuncSetAttribute(rec_kernel, cudaFuncAttributeMaxDynamicSharedMemorySize, rec_smem);

    // layer 0
    sgemm128_abT<<<dim3(48, 8), 256>>>(states, HB, Wih0, HB, b0, pre, N2, HB);
    rec_kernel<<<RECB, RECT, rec_smem>>>(pre, Whh0, seqA, 256);
    // layer 1
    sgemm128_abT<<<dim3(48, 8), 256>>>(seqA, D2, Wih12, D2, b12, pre, N2, D2);
    rec_kernel<<<RECB, RECT, rec_smem>>>(pre, Whh12, seqB, 256);
    // layer 2
    sgemm128_abT<<<dim3(48, 8), 256>>>(seqB, D2, Wih12 + (size_t)2 * 3072 * D2, D2,
                                       b12 + 6144, pre, N2, D2);
    rec_kernel<<<RECB, RECT, rec_smem>>>(pre, Whh12 + (size_t)2 * 3072 * HB, seqA, 256);
    // tanh
    tanh4_kernel<<<(1024 * D2 / 4 + 255) / 256, 256>>>(seqA, 1024 * D2 / 4);
    // attention projections
    sgemm128_abT<<<dim3(6, 2), 256>>>(actions, HB, attnW1, 2304, attnb1, hq, HB, HB);
    sgemm128_abT<<<dim3(6, 8), 256>>>(seqA, D2, attnW1 + HB, 2304, nullptr, hk, HB, D2);
    // scores + softmax
    scores_kernel<<<256, 256>>>(hq, hk, attnW2, attnb2, amask, smask, P);
    // states_feat = P @ out  (batched per b)
    gemm_ab64<<<dim3(24, 1, 4), 256>>>(P, 256, (size_t)64 * 256,
                                       seqA, D2, (size_t)256 * D2,
                                       sf, D2, (size_t)64 * D2, 256);
    // tmpT = sf @ weight^T   [256][2304]
    sgemm128_abT<<<dim3(18, 2), 256>>>(sf, D2, weight, D2, nullptr, tmpT, 2304, D2);
    // adv + final
    adv_kernel<<<256, 256>>>(tmpT, actions, bias, adv);
    final_kernel<<<4, 256>>>(sf, adv, valW, valb, amask, out);
}

// round 4
// speedup vs baseline: 1.2247x; 1.2247x over previous
#include <cuda_runtime.h>
#include <cstdint>

#define HB 768
#define N2 6144
#define D2 1536
#define RECB 128
#define RECT 384

// ----------------------------- scratch (device globals; allocation-free) ----
__device__ float g_pre [1024 * N2];
__device__ float g_seqA[1024 * D2];
__device__ float g_seqB[1024 * D2];
__device__ float g_hbuf[2 * 2 * 4 * HB];   // [parity][dir][b][HB]
__device__ float g_hq  [256 * HB];
__device__ float g_hk  [1024 * HB];
__device__ float g_P   [256 * 256];
__device__ float g_sf  [256 * D2];
__device__ float g_tmpT[256 * 2304];
__device__ float g_adv [256 * 3];
__device__ volatile unsigned g_gen;
__device__ unsigned g_cnt;

// ---------------------------------------------------------------------------
// TF32 tensor-core GEMM 128x128x16: C = A @ B^T (+bias).
// A:[M,K] rm lda, B:[N,K] rm ldb. 256 thr = 8 warps (4M x 2N), warp tile
// 32x64 via mma.sync.m16n8k8.tf32. M,N multiples of 128, K multiple of 16.
// smem k-major, XOR-swizzled: col ^= ((k>>2)&3)<<3  -> conflict-free LDS/STS.
// ---------------------------------------------------------------------------
__device__ __forceinline__ uint32_t f2tf32(float f)
{
    uint32_t u;
    asm("cvt.rna.tf32.f32 %0, %1;" : "=r"(u) : "f"(f));
    return u;
}
__device__ __forceinline__ void mma_tf32(float* c, const uint32_t* a,
                                         uint32_t b0, uint32_t b1)
{
    asm volatile(
        "mma.sync.aligned.m16n8k8.row.col.f32.tf32.tf32.f32 "
        "{%0,%1,%2,%3}, {%4,%5,%6,%7}, {%8,%9}, {%0,%1,%2,%3};\n"
        : "+f"(c[0]), "+f"(c[1]), "+f"(c[2]), "+f"(c[3])
        : "r"(a[0]), "r"(a[1]), "r"(a[2]), "r"(a[3]), "r"(b0), "r"(b1));
}

__global__ __launch_bounds__(256, 2)
void tf32gemm_abT(const float* __restrict__ A, int lda,
                  const float* __restrict__ B, int ldb,
                  const float* __restrict__ bias,
                  float* __restrict__ C, int ldc, int K)
{
    __shared__ uint32_t As[16][136];
    __shared__ uint32_t Bs[16][136];
    const int tid = threadIdx.x;
    const int m0 = blockIdx.y * 128, n0 = blockIdx.x * 128;
    const int warp = tid >> 5, lane = tid & 31;
    const int wm = warp >> 1, wn = warp & 1;      // 4 x 2 warp grid
    const int gid = lane >> 2, tig = lane & 3;
    const int lrow = tid >> 2, lk = (tid & 3) * 4;
    const int sxor = ((lk >> 2) & 3) << 3;        // same for lk..lk+3

    float c[2][8][4];
#pragma unroll
    for (int mt = 0; mt < 2; mt++)
#pragma unroll
        for (int nt = 0; nt < 8; nt++)
#pragma unroll
            for (int q = 0; q < 4; q++) c[mt][nt][q] = 0.f;

    const float* Ap0 = A + (size_t)(m0 + lrow) * lda + lk;
    const float* Ap1 = A + (size_t)(m0 + 64 + lrow) * lda + lk;
    const float* Bp0 = B + (size_t)(n0 + lrow) * ldb + lk;
    const float* Bp1 = B + (size_t)(n0 + 64 + lrow) * ldb + lk;

    for (int k0 = 0; k0 < K; k0 += 16) {
        float4 a0 = *(const float4*)(Ap0 + k0);
        float4 a1 = *(const float4*)(Ap1 + k0);
        float4 b0 = *(const float4*)(Bp0 + k0);
        float4 b1 = *(const float4*)(Bp1 + k0);
        __syncthreads();
        {
            const int c0a = lrow ^ sxor, c1a = (64 + lrow) ^ sxor;
            As[lk+0][c0a] = f2tf32(a0.x); As[lk+1][c0a] = f2tf32(a0.y);
            As[lk+2][c0a] = f2tf32(a0.z); As[lk+3][c0a] = f2tf32(a0.w);
            As[lk+0][c1a] = f2tf32(a1.x); As[lk+1][c1a] = f2tf32(a1.y);
            As[lk+2][c1a] = f2tf32(a1.z); As[lk+3][c1a] = f2tf32(a1.w);
            Bs[lk+0][c0a] = f2tf32(b0.x); Bs[lk+1][c0a] = f2tf32(b0.y);
            Bs[lk+2][c0a] = f2tf32(b0.z); Bs[lk+3][c0a] = f2tf32(b0.w);
            Bs[lk+0][c1a] = f2tf32(b1.x); Bs[lk+1][c1a] = f2tf32(b1.y);
            Bs[lk+2][c1a] = f2tf32(b1.z); Bs[lk+3][c1a] = f2tf32(b1.w);
        }
        __syncthreads();
#pragma unroll
        for (int ks = 0; ks < 2; ks++) {
            const int r0 = ks * 8 + tig;        // k rows for frag half 0
            const int r1 = ks * 8 + 4 + tig;    // k rows for frag half 1
            const int x0 = ((r0 >> 2) & 3) << 3;
            const int x1 = ((r1 >> 2) & 3) << 3;
            uint32_t af[2][4];
#pragma unroll
            for (int mt = 0; mt < 2; mt++) {
                const int mb = wm * 32 + mt * 16;
                af[mt][0] = As[r0][(mb + gid) ^ x0];
                af[mt][1] = As[r0][(mb + 8 + gid) ^ x0];
                af[mt][2] = As[r1][(mb + gid) ^ x1];
                af[mt][3] = As[r1][(mb + 8 + gid) ^ x1];
            }
#pragma unroll
            for (int nt = 0; nt < 8; nt++) {
                const int nb = wn * 64 + nt * 8;
                uint32_t bf0 = Bs[r0][(nb + gid) ^ x0];
                uint32_t bf1 = Bs[r1][(nb + gid) ^ x1];
                mma_tf32(c[0][nt], af[0], bf0, bf1);
                mma_tf32(c[1][nt], af[1], bf0, bf1);
            }
        }
    }
#pragma unroll
    for (int mt = 0; mt < 2; mt++) {
        const int row = m0 + wm * 32 + mt * 16 + gid;
#pragma unroll
        for (int nt = 0; nt < 8; nt++) {
            const int col = n0 + wn * 64 + nt * 8 + tig * 2;
            float bv0 = bias ? bias[col] : 0.f;
            float bv1 = bias ? bias[col + 1] : 0.f;
            float2 v0 = make_float2(c[mt][nt][0] + bv0, c[mt][nt][1] + bv1);
            float2 v1 = make_float2(c[mt][nt][2] + bv0, c[mt][nt][3] + bv1);
            *(float2*)&C[(size_t)row * ldc + col] = v0;
            *(float2*)&C[(size_t)(row + 8) * ldc + col] = v1;
        }
    }
}

// ---------------------------------------------------------------------------
// Batched GEMM 64x64x16: C = A @ B (A:[M,K] rm, B:[K,N] rm). For P @ out.
// ---------------------------------------------------------------------------
__global__ __launch_bounds__(256)
void gemm_ab64(const float* __restrict__ Ab, int lda, size_t strA,
               const float* __restrict__ Bb, int ldb, size_t strB,
               float* __restrict__ Cb, int ldc, size_t strC, int K)
{
    const float* A = Ab + strA * blockIdx.z;
    const float* B = Bb + strB * blockIdx.z;
    float* C = Cb + strC * blockIdx.z;
    __shared__ float As[16][68];
    __shared__ float Bs[16][68];
    const int tid = threadIdx.x;
    const int m0 = blockIdx.y * 64, n0 = blockIdx.x * 64;
    const int tx = tid & 15, ty = tid >> 4;
    const int lrow = tid >> 2, lk = (tid & 3) * 4;
    const int bkk = tid >> 4, bnq = (tid & 15) * 4;

    float acc[4][4];
#pragma unroll
    for (int i = 0; i < 4; i++)
#pragma unroll
        for (int j = 0; j < 4; j++) acc[i][j] = 0.f;

    for (int k0 = 0; k0 < K; k0 += 16) {
        float4 a0 = *(const float4*)&A[(size_t)(m0 + lrow) * lda + k0 + lk];
        float4 b0 = *(const float4*)&B[(size_t)(k0 + bkk) * ldb + n0 + bnq];
        __syncthreads();
        As[lk+0][lrow]=a0.x; As[lk+1][lrow]=a0.y; As[lk+2][lrow]=a0.z; As[lk+3][lrow]=a0.w;
        *(float4*)&Bs[bkk][bnq] = b0;
        __syncthreads();
#pragma unroll
        for (int kk = 0; kk < 16; kk++) {
            float ar[4], br[4];
            *(float4*)&ar[0] = *(const float4*)&As[kk][ty * 4];
            *(float4*)&br[0] = *(const float4*)&Bs[kk][tx * 4];
#pragma unroll
            for (int i = 0; i < 4; i++)
#pragma unroll
                for (int j = 0; j < 4; j++) acc[i][j] += ar[i] * br[j];
        }
    }
#pragma unroll
    for (int i = 0; i < 4; i++) {
        float4 v = make_float4(acc[i][0], acc[i][1], acc[i][2], acc[i][3]);
        *(float4*)&C[(size_t)(m0 + ty * 4 + i) * ldc + n0 + tx * 4] = v;
    }
}

// ---------------------------------------------------------------------------
// Persistent BiLSTM recurrence. 128 CTAs x 384 thr. CTA: dir = bx>>6,
// cells [c0,c0+12), all 4 gates (48 Whh rows in SMEM). Grid barrier per step.
// ---------------------------------------------------------------------------
__device__ __forceinline__ float sigf(float x) { return 1.f / (1.f + expf(-x)); }

__global__ __launch_bounds__(RECT, 1)
void rec_kernel(const float* __restrict__ pre,   // [1024][6144]
                const float* __restrict__ whh,   // [2][3072][768]
                float* __restrict__ out,         // [1024][1536]
                int T)
{
    extern __shared__ float sm[];
    float* sW     = sm;               // [48][768]
    float* sh     = sW + 48 * 768;    // [4][768]
    float* sgates = sh + 4 * 768;     // [48][4]
    float* spre   = sgates + 192;     // [48][4]
    float* scst   = spre + 192;       // [48]
    __shared__ unsigned s_gen;

    const int tid = threadIdx.x;
    const int dir = blockIdx.x >> 6;
    const int c0  = (blockIdx.x & 63) * 12;
    const int rg  = tid >> 5, ks = tid & 31;

    for (int idx = tid; idx < 9216; idx += RECT) {
        int r = idx / 192, kc = (idx - r * 192) * 4;
        int g = r / 12, jj = r - g * 12;
        *(float4*)&sW[r * 768 + kc] =
            *(const float4*)&whh[((size_t)dir * 3072 + g * 768 + c0 + jj) * 768 + kc];
    }
    if (tid < 48) {
        scst[tid] = 0.f;
        int jj = tid >> 2, b = tid & 3;
        __stcg(&g_hbuf[((0 * 2 + dir) * 4 + b) * HB + c0 + jj], 0.f);
    }
    if (tid == 0) s_gen = g_gen;

#define GB() do { \
    __syncthreads(); \
    if (tid == 0) { \
        __threadfence(); \
        unsigned tgt = s_gen + 1; s_gen = tgt; \
        if (atomicAdd(&g_cnt, 1u) == RECB - 1u) { \
            atomicExch(&g_cnt, 0u); __threadfence(); g_gen = tgt; \
        } else { \
            while ((int)(g_gen - tgt) < 0) {} __threadfence(); \
        } \
    } \
    __syncthreads(); } while (0)

    GB();

    int par = 0;
    for (int step = 0; step < T; step++) {
        const int t = (dir == 0) ? step : (T - 1 - step);

        float prev = 0.f;
        if (tid < 192) {
            int r = tid >> 2, b = tid & 3;
            int g = r / 12, jj = r - g * 12;
            prev = __ldg(&pre[(size_t)(b * 256 + t) * N2 + dir * 3072 + g * 768 + c0 + jj]);
        }
        for (int idx = tid; idx < 768; idx += RECT) {
            int b = idx / 192, kc = (idx - b * 192) * 4;
            *(float4*)&sh[b * 768 + kc] =
                __ldcg((const float4*)&g_hbuf[((par * 2 + dir) * 4 + b) * HB + kc]);
        }
        __syncthreads();

        float acc[4][4];
#pragma unroll
        for (int i = 0; i < 4; i++)
#pragma unroll
            for (int b = 0; b < 4; b++) acc[i][b] = 0.f;
        const float* wb = sW + (rg * 4) * 768;
#pragma unroll
        for (int it = 0; it < 6; it++) {
            int ko = it * 128 + ks * 4;
            float4 w0 = *(const float4*)(wb + 0 * 768 + ko);
            float4 w1 = *(const float4*)(wb + 1 * 768 + ko);
            float4 w2 = *(const float4*)(wb + 2 * 768 + ko);
            float4 w3 = *(const float4*)(wb + 3 * 768 + ko);
            float4 h0 = *(const float4*)(sh + 0 * 768 + ko);
            float4 h1 = *(const float4*)(sh + 1 * 768 + ko);
            float4 h2 = *(const float4*)(sh + 2 * 768 + ko);
            float4 h3 = *(const float4*)(sh + 3 * 768 + ko);
#define FMA16(I, W) \
            acc[I][0] += W.x*h0.x + W.y*h0.y + W.z*h0.z + W.w*h0.w; \
            acc[I][1] += W.x*h1.x + W.y*h1.y + W.z*h1.z + W.w*h1.w; \
            acc[I][2] += W.x*h2.x + W.y*h2.y + W.z*h2.z + W.w*h2.w; \
            acc[I][3] += W.x*h3.x + W.y*h3.y + W.z*h3.z + W.w*h3.w;
            FMA16(0, w0) FMA16(1, w1) FMA16(2, w2) FMA16(3, w3)
#undef FMA16
        }
#pragma unroll
        for (int o = 16; o; o >>= 1)
#pragma unroll
            for (int i = 0; i < 4; i++)
#pragma unroll
                for (int b = 0; b < 4; b++)
                    acc[i][b] += __shfl_xor_sync(0xffffffffu, acc[i][b], o);
        if (ks == 0) {
#pragma unroll
            for (int i = 0; i < 4; i++)
#pragma unroll
                for (int b = 0; b < 4; b++)
                    sgates[(rg * 4 + i) * 4 + b] = acc[i][b];
        }
        if (tid < 192) spre[tid] = prev;
        __syncthreads();

        if (tid < 48) {
            int jj = tid >> 2, b = tid & 3;
            float xi = sgates[(0 * 12 + jj) * 4 + b] + spre[(0 * 12 + jj) * 4 + b];
            float xf = sgates[(1 * 12 + jj) * 4 + b] + spre[(1 * 12 + jj) * 4 + b];
            float xg = sgates[(2 * 12 + jj) * 4 + b] + spre[(2 * 12 + jj) * 4 + b];
            float xo = sgates[(3 * 12 + jj) * 4 + b] + spre[(3 * 12 + jj) * 4 + b];
            float cc = sigf(xf) * scst[tid] + sigf(xi) * tanhf(xg);
            float h = sigf(xo) * tanhf(cc);
            scst[tid] = cc;
            int cell = c0 + jj;
            __stcg(&g_hbuf[(((par ^ 1) * 2 + dir) * 4 + b) * HB + cell], h);
            out[(size_t)(b * 256 + t) * D2 + dir * HB + cell] = h;
        }
        GB();
        par ^= 1;
    }
#undef GB
}

// ---------------------------------------------------------------------------
__global__ void tanh4_kernel(float* __restrict__ x, int n4)
{
    int i = blockIdx.x * blockDim.x + threadIdx.x;
    if (i < n4) {
        float4 v = ((float4*)x)[i];
        v.x = tanhf(v.x); v.y = tanhf(v.y); v.z = tanhf(v.z); v.w = tanhf(v.w);
        ((float4*)x)[i] = v;
    }
}

__device__ __forceinline__ float blockReduceSum(float v, float* sr)
{
    __syncthreads();
#pragma unroll
    for (int o = 16; o; o >>= 1) v += __shfl_xor_sync(0xffffffffu, v, o);
    int lane = threadIdx.x & 31, w = threadIdx.x >> 5;
    if (lane == 0) sr[w] = v;
    __syncthreads();
    if (w == 0) {
        int nw = (blockDim.x + 31) >> 5;
        v = (lane < nw) ? sr[lane] : 0.f;
#pragma unroll
        for (int o = 16; o; o >>= 1) v += __shfl_xor_sync(0xffffffffu, v, o);
        if (lane == 0) sr[0] = v;
    }
    __syncthreads();
    return sr[0];
}

// scores + softmax: block per (b,q); thread = k.
__global__ __launch_bounds__(256)
void scores_kernel(const float* __restrict__ hq, const float* __restrict__ hk,
                   const float* __restrict__ w2, const float* __restrict__ b2p,
                   const float* __restrict__ am, const float* __restrict__ smk,
                   float* __restrict__ P)
{
    __shared__ float shq[768], sw2[768], shk[256 * 33], sr[32];
    const int tid = threadIdx.x, bq = blockIdx.x;
    const int b = bq >> 6, q = bq & 63;
    for (int i = tid; i < 768; i += 256) { shq[i] = hq[bq * 768 + i]; sw2[i] = w2[i]; }
    float acc = 0.f;
    for (int e0 = 0; e0 < 768; e0 += 32) {
        __syncthreads();
        for (int idx = tid; idx < 256 * 32; idx += 256) {
            int k = idx >> 5, e = idx & 31;
            shk[k * 33 + e] = hk[(size_t)((b << 8) + k) * 768 + e0 + e];
        }
        __syncthreads();
#pragma unroll 8
        for (int e = 0; e < 32; e++) {
            float v = shq[e0 + e] + shk[tid * 33 + e];
            acc += fmaxf(v, 0.f) * sw2[e0 + e];
        }
    }
    float score = acc + b2p[0];
    float m = am[b * 64 + q] * smk[b * 256 + tid];
    float a = (m == 0.f) ? 0.f : expf(score);
    float s = blockReduceSum(a, sr);
    P[bq * 256 + tid] = a / fmaxf(s, 2e-15f);
}

__global__ __launch_bounds__(256)
void adv_kernel(const float* __restrict__ tmpT, const float* __restrict__ act,
                const float* __restrict__ bias, float* __restrict__ adv)
{
    __shared__ float sa[768], sr[32];
    const int tid = threadIdx.x, bq = blockIdx.x;
    for (int i = tid; i < 768; i += 256) sa[i] = act[(size_t)bq * 768 + i];
    for (int l = 0; l < 3; l++) {
        float acc = 0.f;
        for (int h = tid; h < 768; h += 256)
            acc += tmpT[(size_t)bq * 2304 + l * 768 + h] * sa[h];
        float s = blockReduceSum(acc, sr);
        if (tid == 0) adv[bq * 3 + l] = s + bias[l];
    }
}

__global__ __launch_bounds__(256)
void final_kernel(const float* __restrict__ sf, const float* __restrict__ adv,
                  const float* __restrict__ valW, const float* __restrict__ valbp,
                  const float* __restrict__ am, float* __restrict__ out)
{
    __shared__ float sr[32];
    const int tid = threadIdx.x, b = blockIdx.x;
    float accv = 0.f;
    for (int d = tid; d < D2; d += 256) {
        float s = 0.f;
        for (int q = 0; q < 64; q++) s += sf[(size_t)(b * 64 + q) * D2 + d];
        accv += s * valW[d];
    }
    accv = blockReduceSum(accv, sr);
    float nv = (tid < 64) ? am[b * 64 + tid] : 0.f;
    nv = blockReduceSum(nv, sr);
    float asum = 0.f;
    for (int i = tid; i < 192; i += 256) asum += adv[b * 192 + i];
    asum = blockReduceSum(asum, sr);
    float val = accv / nv + valbp[0];
    float mean = asum / 192.f;
    for (int i = tid; i < 192; i += 256)
        out[b * 192 + i] = val + adv[b * 192 + i] - mean;
}

// ---------------------------------------------------------------------------
extern "C" void kernel_launch(void* const* d_in, const int* in_sizes, int n_in,
                              void* d_out, int out_size)
{
    const float* states  = (const float*)d_in[0];
    const float* smask   = (const float*)d_in[1];
    const float* actions = (const float*)d_in[2];
    const float* amask   = (const float*)d_in[3];
    const float* Wih0    = (const float*)d_in[4];
    const float* Whh0    = (const float*)d_in[5];
    const float* b0      = (const float*)d_in[6];
    const float* Wih12   = (const float*)d_in[7];
    const float* Whh12   = (const float*)d_in[8];
    const float* b12     = (const float*)d_in[9];
    const float* attnW1  = (const float*)d_in[10];
    const float* attnb1  = (const float*)d_in[11];
    const float* attnW2  = (const float*)d_in[12];
    const float* attnb2  = (const float*)d_in[13];
    const float* valW    = (const float*)d_in[14];
    const float* valb    = (const float*)d_in[15];
    const float* weight  = (const float*)d_in[16];
    const float* bias    = (const float*)d_in[17];
    float* out = (float*)d_out;

    float *pre, *seqA, *seqB, *hq, *hk, *P, *sf, *tmpT, *adv;
    cudaGetSymbolAddress((void**)&pre,  g_pre);
    cudaGetSymbolAddress((void**)&seqA, g_seqA);
    cudaGetSymbolAddress((void**)&seqB, g_seqB);
    cudaGetSymbolAddress((void**)&hq,   g_hq);
    cudaGetSymbolAddress((void**)&hk,   g_hk);
    cudaGetSymbolAddress((void**)&P,    g_P);
    cudaGetSymbolAddress((void**)&sf,   g_sf);
    cudaGetSymbolAddress((void**)&tmpT, g_tmpT);
    cudaGetSymbolAddress((void**)&adv,  g_adv);

    const int rec_smem = (48 * 768 + 4 * 768 + 192 + 192 + 48) * 4;
    cudaFuncSetAttribute(rec_kernel, cudaFuncAttributeMaxDynamicSharedMemorySize, rec_smem);

    // layer 0
    tf32gemm_abT<<<dim3(48, 8), 256>>>(states, HB, Wih0, HB, b0, pre, N2, HB);
    rec_kernel<<<RECB, RECT, rec_smem>>>(pre, Whh0, seqA, 256);
    // layer 1
    tf32gemm_abT<<<dim3(48, 8), 256>>>(seqA, D2, Wih12, D2, b12, pre, N2, D2);
    rec_kernel<<<RECB, RECT, rec_smem>>>(pre, Whh12, seqB, 256);
    // layer 2
    tf32gemm_abT<<<dim3(48, 8), 256>>>(seqB, D2, Wih12 + (size_t)2 * 3072 * D2, D2,
                                       b12 + 6144, pre, N2, D2);
    rec_kernel<<<RECB, RECT, rec_smem>>>(pre, Whh12 + (size_t)2 * 3072 * HB, seqA, 256);
    // tanh
    tanh4_kernel<<<(1024 * D2 / 4 + 255) / 256, 256>>>(seqA, 1024 * D2 / 4);
    // attention projections
    tf32gemm_abT<<<dim3(6, 2), 256>>>(actions, HB, attnW1, 2304, attnb1, hq, HB, HB);
    tf32gemm_abT<<<dim3(6, 8), 256>>>(seqA, D2, attnW1 + HB, 2304, nullptr, hk, HB, D2);
    // scores + softmax
    scores_kernel<<<256, 256>>>(hq, hk, attnW2, attnb2, amask, smask, P);
    // states_feat = P @ out  (batched per b)
    gemm_ab64<<<dim3(24, 1, 4), 256>>>(P, 256, (size_t)64 * 256,
                                       seqA, D2, (size_t)256 * D2,
                                       sf, D2, (size_t)64 * D2, 256);
    // tmpT = sf @ weight^T
    tf32gemm_abT<<<dim3(18, 2), 256>>>(sf, D2, weight, D2, nullptr, tmpT, 2304, D2);
    // adv + final
    adv_kernel<<<256, 256>>>(tmpT, actions, bias, adv);
    final_kernel<<<4, 256>>>(sf, adv, valW, valb, amask, out);
}

// round 5
// speedup vs baseline: 1.2286x; 1.0032x over previous
#include <cuda_runtime.h>
#include <cstdint>

#define HB 768
#define N2 6144
#define D2 1536
#define RECB 128
#define RECT 384

// ----------------------------- scratch (device globals; allocation-free) ----
__device__ float g_pre [1024 * N2];
__device__ float g_seqA[1024 * D2];
__device__ float g_seqB[1024 * D2];
__device__ float g_hbuf[2 * 2 * 4 * HB];   // [parity][dir][b][HB]
__device__ float g_hq  [256 * HB];
__device__ float g_hk  [1024 * HB];
__device__ float g_P   [256 * 256];
__device__ float g_sf  [256 * D2];
__device__ float g_tmpT[256 * 2304];
__device__ float g_adv [256 * 3];
__device__ unsigned g_flags[RECB * 32];    // 128B-strided per-CTA epoch flags

// ---------------------------------------------------------------------------
// TF32 tensor-core GEMM 128x128x16: C = A @ B^T (+bias).
// ---------------------------------------------------------------------------
__device__ __forceinline__ uint32_t f2tf32(float f)
{
    uint32_t u;
    asm("cvt.rna.tf32.f32 %0, %1;" : "=r"(u) : "f"(f));
    return u;
}
__device__ __forceinline__ void mma_tf32(float* c, const uint32_t* a,
                                         uint32_t b0, uint32_t b1)
{
    asm volatile(
        "mma.sync.aligned.m16n8k8.row.col.f32.tf32.tf32.f32 "
        "{%0,%1,%2,%3}, {%4,%5,%6,%7}, {%8,%9}, {%0,%1,%2,%3};\n"
        : "+f"(c[0]), "+f"(c[1]), "+f"(c[2]), "+f"(c[3])
        : "r"(a[0]), "r"(a[1]), "r"(a[2]), "r"(a[3]), "r"(b0), "r"(b1));
}

__global__ __launch_bounds__(256, 2)
void tf32gemm_abT(const float* __restrict__ A, int lda,
                  const float* __restrict__ B, int ldb,
                  const float* __restrict__ bias,
                  float* __restrict__ C, int ldc, int K)
{
    __shared__ uint32_t As[16][136];
    __shared__ uint32_t Bs[16][136];
    const int tid = threadIdx.x;
    const int m0 = blockIdx.y * 128, n0 = blockIdx.x * 128;
    const int warp = tid >> 5, lane = tid & 31;
    const int wm = warp >> 1, wn = warp & 1;
    const int gid = lane >> 2, tig = lane & 3;
    const int lrow = tid >> 2, lk = (tid & 3) * 4;
    const int sxor = ((lk >> 2) & 3) << 3;

    float c[2][8][4];
#pragma unroll
    for (int mt = 0; mt < 2; mt++)
#pragma unroll
        for (int nt = 0; nt < 8; nt++)
#pragma unroll
            for (int q = 0; q < 4; q++) c[mt][nt][q] = 0.f;

    const float* Ap0 = A + (size_t)(m0 + lrow) * lda + lk;
    const float* Ap1 = A + (size_t)(m0 + 64 + lrow) * lda + lk;
    const float* Bp0 = B + (size_t)(n0 + lrow) * ldb + lk;
    const float* Bp1 = B + (size_t)(n0 + 64 + lrow) * ldb + lk;

    for (int k0 = 0; k0 < K; k0 += 16) {
        float4 a0 = *(const float4*)(Ap0 + k0);
        float4 a1 = *(const float4*)(Ap1 + k0);
        float4 b0 = *(const float4*)(Bp0 + k0);
        float4 b1 = *(const float4*)(Bp1 + k0);
        __syncthreads();
        {
            const int c0a = lrow ^ sxor, c1a = (64 + lrow) ^ sxor;
            As[lk+0][c0a] = f2tf32(a0.x); As[lk+1][c0a] = f2tf32(a0.y);
            As[lk+2][c0a] = f2tf32(a0.z); As[lk+3][c0a] = f2tf32(a0.w);
            As[lk+0][c1a] = f2tf32(a1.x); As[lk+1][c1a] = f2tf32(a1.y);
            As[lk+2][c1a] = f2tf32(a1.z); As[lk+3][c1a] = f2tf32(a1.w);
            Bs[lk+0][c0a] = f2tf32(b0.x); Bs[lk+1][c0a] = f2tf32(b0.y);
            Bs[lk+2][c0a] = f2tf32(b0.z); Bs[lk+3][c0a] = f2tf32(b0.w);
            Bs[lk+0][c1a] = f2tf32(b1.x); Bs[lk+1][c1a] = f2tf32(b1.y);
            Bs[lk+2][c1a] = f2tf32(b1.z); Bs[lk+3][c1a] = f2tf32(b1.w);
        }
        __syncthreads();
#pragma unroll
        for (int ks = 0; ks < 2; ks++) {
            const int r0 = ks * 8 + tig;
            const int r1 = ks * 8 + 4 + tig;
            const int x0 = ((r0 >> 2) & 3) << 3;
            const int x1 = ((r1 >> 2) & 3) << 3;
            uint32_t af[2][4];
#pragma unroll
            for (int mt = 0; mt < 2; mt++) {
                const int mb = wm * 32 + mt * 16;
                af[mt][0] = As[r0][(mb + gid) ^ x0];
                af[mt][1] = As[r0][(mb + 8 + gid) ^ x0];
                af[mt][2] = As[r1][(mb + gid) ^ x1];
                af[mt][3] = As[r1][(mb + 8 + gid) ^ x1];
            }
#pragma unroll
            for (int nt = 0; nt < 8; nt++) {
                const int nb = wn * 64 + nt * 8;
                uint32_t bf0 = Bs[r0][(nb + gid) ^ x0];
                uint32_t bf1 = Bs[r1][(nb + gid) ^ x1];
                mma_tf32(c[0][nt], af[0], bf0, bf1);
                mma_tf32(c[1][nt], af[1], bf0, bf1);
            }
        }
    }
#pragma unroll
    for (int mt = 0; mt < 2; mt++) {
        const int row = m0 + wm * 32 + mt * 16 + gid;
#pragma unroll
        for (int nt = 0; nt < 8; nt++) {
            const int col = n0 + wn * 64 + nt * 8 + tig * 2;
            float bv0 = bias ? bias[col] : 0.f;
            float bv1 = bias ? bias[col + 1] : 0.f;
            float2 v0 = make_float2(c[mt][nt][0] + bv0, c[mt][nt][1] + bv1);
            float2 v1 = make_float2(c[mt][nt][2] + bv0, c[mt][nt][3] + bv1);
            *(float2*)&C[(size_t)row * ldc + col] = v0;
            *(float2*)&C[(size_t)(row + 8) * ldc + col] = v1;
        }
    }
}

// ---------------------------------------------------------------------------
// Batched GEMM 64x64x16: C = A @ B (for P @ out).
// ---------------------------------------------------------------------------
__global__ __launch_bounds__(256)
void gemm_ab64(const float* __restrict__ Ab, int lda, size_t strA,
               const float* __restrict__ Bb, int ldb, size_t strB,
               float* __restrict__ Cb, int ldc, size_t strC, int K)
{
    const float* A = Ab + strA * blockIdx.z;
    const float* B = Bb + strB * blockIdx.z;
    float* C = Cb + strC * blockIdx.z;
    __shared__ float As[16][68];
    __shared__ float Bs[16][68];
    const int tid = threadIdx.x;
    const int m0 = blockIdx.y * 64, n0 = blockIdx.x * 64;
    const int tx = tid & 15, ty = tid >> 4;
    const int lrow = tid >> 2, lk = (tid & 3) * 4;
    const int bkk = tid >> 4, bnq = (tid & 15) * 4;

    float acc[4][4];
#pragma unroll
    for (int i = 0; i < 4; i++)
#pragma unroll
        for (int j = 0; j < 4; j++) acc[i][j] = 0.f;

    for (int k0 = 0; k0 < K; k0 += 16) {
        float4 a0 = *(const float4*)&A[(size_t)(m0 + lrow) * lda + k0 + lk];
        float4 b0 = *(const float4*)&B[(size_t)(k0 + bkk) * ldb + n0 + bnq];
        __syncthreads();
        As[lk+0][lrow]=a0.x; As[lk+1][lrow]=a0.y; As[lk+2][lrow]=a0.z; As[lk+3][lrow]=a0.w;
        *(float4*)&Bs[bkk][bnq] = b0;
        __syncthreads();
#pragma unroll
        for (int kk = 0; kk < 16; kk++) {
            float ar[4], br[4];
            *(float4*)&ar[0] = *(const float4*)&As[kk][ty * 4];
            *(float4*)&br[0] = *(const float4*)&Bs[kk][tx * 4];
#pragma unroll
            for (int i = 0; i < 4; i++)
#pragma unroll
                for (int j = 0; j < 4; j++) acc[i][j] += ar[i] * br[j];
        }
    }
#pragma unroll
    for (int i = 0; i < 4; i++) {
        float4 v = make_float4(acc[i][0], acc[i][1], acc[i][2], acc[i][3]);
        *(float4*)&C[(size_t)(m0 + ty * 4 + i) * ldc + n0 + tx * 4] = v;
    }
}

// ---------------------------------------------------------------------------
// Persistent BiLSTM recurrence v2.
// 128 CTAs x 384 thr; CTA: dir = bx>>6, cells [c0,c0+12); warp rg = cell
// c0+rg, all 4 gates (rows g*12+rg of the CTA's 48-row Whh smem slice).
// Per-direction distributed flag barrier (64 CTAs each, 128B-strided flags,
// wrap-safe epochs -> deterministic across graph replays). c-state lives in
// registers of lanes 0..3 (lane = batch).
// ---------------------------------------------------------------------------
__device__ __forceinline__ float sigf(float x) { return 1.f / (1.f + expf(-x)); }

__global__ __launch_bounds__(RECT, 1)
void rec_kernel(const float* __restrict__ pre,   // [1024][6144]
                const float* __restrict__ whh,   // [2][3072][768]
                float* __restrict__ out,         // [1024][1536]
                int T, int do_tanh)
{
    extern __shared__ float sm[];
    float* sW = sm;               // [48][768]
    float* sh = sW + 48 * 768;    // [4][768]

    const int tid = threadIdx.x;
    const int bx  = blockIdx.x;
    const int dir = bx >> 6;
    const int c0  = (bx & 63) * 12;
    const int rg  = tid >> 5, ks = tid & 31;
    const int grp = dir << 6;                      // flag group base CTA

    // stage Whh slice: row r=g*12+jj <- whh[dir][g*768+c0+jj][:]
    for (int idx = tid; idx < 9216; idx += RECT) {
        int r = idx / 192, kc = (idx - r * 192) * 4;
        int g = r / 12, jj = r - g * 12;
        *(float4*)&sW[r * 768 + kc] =
            *(const float4*)&whh[((size_t)dir * 3072 + g * 768 + c0 + jj) * 768 + kc];
    }
    // zero h parity 0 for our cells (warp rg, lanes 0..3 = batch)
    if (ks < 4)
        __stcg(&g_hbuf[((0 * 2 + dir) * 4 + ks) * HB + c0 + rg], 0.f);

    const unsigned base = *(volatile unsigned*)&g_flags[bx * 32];

#define BAR(TGT) do {                                                     \
    __syncthreads();                                                      \
    if (tid == 0) {                                                       \
        __threadfence();                                                  \
        *(volatile unsigned*)&g_flags[bx * 32] = (TGT);                   \
    }                                                                     \
    if (tid < 64) {                                                       \
        volatile unsigned* fp = &g_flags[(grp + tid) * 32];               \
        while ((int)(*fp - (TGT)) < 0) {}                                 \
        __threadfence();                                                  \
    }                                                                     \
    __syncthreads(); } while (0)

    BAR(base + 1);   // h zeros visible within this direction group

    float creg = 0.f;        // cell state for (cell c0+rg, batch ks) on ks<4
    int par = 0;
    for (int step = 0; step < T; step++) {
        const int t = (dir == 0) ? step : (T - 1 - step);

        // prefetch pre-activations for gate lanes (lane ks<4 = batch)
        float pg0 = 0.f, pg1 = 0.f, pg2 = 0.f, pg3 = 0.f;
        if (ks < 4) {
            const float* pp = pre + (size_t)(ks * 256 + t) * N2 + dir * 3072 + c0 + rg;
            pg0 = __ldg(pp + 0 * 768);
            pg1 = __ldg(pp + 1 * 768);
            pg2 = __ldg(pp + 2 * 768);
            pg3 = __ldg(pp + 3 * 768);
        }
        // stage h from L2 (written by other SMs)
        for (int idx = tid; idx < 768; idx += RECT) {
            int b = idx / 192, kc = (idx - b * 192) * 4;
            *(float4*)&sh[b * 768 + kc] =
                __ldcg((const float4*)&g_hbuf[((par * 2 + dir) * 4 + b) * HB + kc]);
        }
        __syncthreads();

        // warp rg: gates g=0..3 of cell c0+rg, batches 0..3; k over lanes
        float acc[4][4];
#pragma unroll
        for (int g = 0; g < 4; g++)
#pragma unroll
            for (int b = 0; b < 4; b++) acc[g][b] = 0.f;
        const float* w0p = sW + (0 * 12 + rg) * 768;
        const float* w1p = sW + (1 * 12 + rg) * 768;
        const float* w2p = sW + (2 * 12 + rg) * 768;
        const float* w3p = sW + (3 * 12 + rg) * 768;
#pragma unroll
        for (int it = 0; it < 6; it++) {
            int ko = it * 128 + ks * 4;
            float4 w0 = *(const float4*)(w0p + ko);
            float4 w1 = *(const float4*)(w1p + ko);
            float4 w2 = *(const float4*)(w2p + ko);
            float4 w3 = *(const float4*)(w3p + ko);
            float4 h0 = *(const float4*)(sh + 0 * 768 + ko);
            float4 h1 = *(const float4*)(sh + 1 * 768 + ko);
            float4 h2 = *(const float4*)(sh + 2 * 768 + ko);
            float4 h3 = *(const float4*)(sh + 3 * 768 + ko);
#define FMA16(G, W) \
            acc[G][0] += W.x*h0.x + W.y*h0.y + W.z*h0.z + W.w*h0.w; \
            acc[G][1] += W.x*h1.x + W.y*h1.y + W.z*h1.z + W.w*h1.w; \
            acc[G][2] += W.x*h2.x + W.y*h2.y + W.z*h2.z + W.w*h2.w; \
            acc[G][3] += W.x*h3.x + W.y*h3.y + W.z*h3.z + W.w*h3.w;
            FMA16(0, w0) FMA16(1, w1) FMA16(2, w2) FMA16(3, w3)
#undef FMA16
        }
        // butterfly: every lane ends with full sums
#pragma unroll
        for (int o = 16; o; o >>= 1)
#pragma unroll
            for (int g = 0; g < 4; g++)
#pragma unroll
                for (int b = 0; b < 4; b++)
                    acc[g][b] += __shfl_xor_sync(0xffffffffu, acc[g][b], o);

        if (ks < 4) {
            const int b = ks;
            float xi = acc[0][b] + pg0;
            float xf = acc[1][b] + pg1;
            float xg = acc[2][b] + pg2;
            float xo = acc[3][b] + pg3;
            creg = sigf(xf) * creg + sigf(xi) * tanhf(xg);
            float h = sigf(xo) * tanhf(creg);
            __stcg(&g_hbuf[(((par ^ 1) * 2 + dir) * 4 + b) * HB + c0 + rg], h);
            out[(size_t)(b * 256 + t) * D2 + dir * HB + c0 + rg] =
                do_tanh ? tanhf(h) : h;
        }
        BAR(base + 2 + step);
        par ^= 1;
    }
#undef BAR
}

// ---------------------------------------------------------------------------
__device__ __forceinline__ float blockReduceSum(float v, float* sr)
{
    __syncthreads();
#pragma unroll
    for (int o = 16; o; o >>= 1) v += __shfl_xor_sync(0xffffffffu, v, o);
    int lane = threadIdx.x & 31, w = threadIdx.x >> 5;
    if (lane == 0) sr[w] = v;
    __syncthreads();
    if (w == 0) {
        int nw = (blockDim.x + 31) >> 5;
        v = (lane < nw) ? sr[lane] : 0.f;
#pragma unroll
        for (int o = 16; o; o >>= 1) v += __shfl_xor_sync(0xffffffffu, v, o);
        if (lane == 0) sr[0] = v;
    }
    __syncthreads();
    return sr[0];
}

// scores + softmax: block per (b,q); thread = k.
__global__ __launch_bounds__(256)
void scores_kernel(const float* __restrict__ hq, const float* __restrict__ hk,
                   const float* __restrict__ w2, const float* __restrict__ b2p,
                   const float* __restrict__ am, const float* __restrict__ smk,
                   float* __restrict__ P)
{
    __shared__ float shq[768], sw2[768], shk[256 * 33], sr[32];
    const int tid = threadIdx.x, bq = blockIdx.x;
    const int b = bq >> 6, q = bq & 63;
    for (int i = tid; i < 768; i += 256) { shq[i] = hq[bq * 768 + i]; sw2[i] = w2[i]; }
    float acc = 0.f;
    for (int e0 = 0; e0 < 768; e0 += 32) {
        __syncthreads();
        for (int idx = tid; idx < 256 * 32; idx += 256) {
            int k = idx >> 5, e = idx & 31;
            shk[k * 33 + e] = hk[(size_t)((b << 8) + k) * 768 + e0 + e];
        }
        __syncthreads();
#pragma unroll 8
        for (int e = 0; e < 32; e++) {
            float v = shq[e0 + e] + shk[tid * 33 + e];
            acc += fmaxf(v, 0.f) * sw2[e0 + e];
        }
    }
    float score = acc + b2p[0];
    float m = am[b * 64 + q] * smk[b * 256 + tid];
    float a = (m == 0.f) ? 0.f : expf(score);
    float s = blockReduceSum(a, sr);
    P[bq * 256 + tid] = a / fmaxf(s, 2e-15f);
}

__global__ __launch_bounds__(256)
void adv_kernel(const float* __restrict__ tmpT, const float* __restrict__ act,
                const float* __restrict__ bias, float* __restrict__ adv)
{
    __shared__ float sa[768], sr[32];
    const int tid = threadIdx.x, bq = blockIdx.x;
    for (int i = tid; i < 768; i += 256) sa[i] = act[(size_t)bq * 768 + i];
    for (int l = 0; l < 3; l++) {
        float acc = 0.f;
        for (int h = tid; h < 768; h += 256)
            acc += tmpT[(size_t)bq * 2304 + l * 768 + h] * sa[h];
        float s = blockReduceSum(acc, sr);
        if (tid == 0) adv[bq * 3 + l] = s + bias[l];
    }
}

__global__ __launch_bounds__(256)
void final_kernel(const float* __restrict__ sf, const float* __restrict__ adv,
                  const float* __restrict__ valW, const float* __restrict__ valbp,
                  const float* __restrict__ am, float* __restrict__ out)
{
    __shared__ float sr[32];
    const int tid = threadIdx.x, b = blockIdx.x;
    float accv = 0.f;
    for (int d = tid; d < D2; d += 256) {
        float s = 0.f;
        for (int q = 0; q < 64; q++) s += sf[(size_t)(b * 64 + q) * D2 + d];
        accv += s * valW[d];
    }
    accv = blockReduceSum(accv, sr);
    float nv = (tid < 64) ? am[b * 64 + tid] : 0.f;
    nv = blockReduceSum(nv, sr);
    float asum = 0.f;
    for (int i = tid; i < 192; i += 256) asum += adv[b * 192 + i];
    asum = blockReduceSum(asum, sr);
    float val = accv / nv + valbp[0];
    float mean = asum / 192.f;
    for (int i = tid; i < 192; i += 256)
        out[b * 192 + i] = val + adv[b * 192 + i] - mean;
}

// ---------------------------------------------------------------------------
extern "C" void kernel_launch(void* const* d_in, const int* in_sizes, int n_in,
                              void* d_out, int out_size)
{
    const float* states  = (const float*)d_in[0];
    const float* smask   = (const float*)d_in[1];
    const float* actions = (const float*)d_in[2];
    const float* amask   = (const float*)d_in[3];
    const float* Wih0    = (const float*)d_in[4];
    const float* Whh0    = (const float*)d_in[5];
    const float* b0      = (const float*)d_in[6];
    const float* Wih12   = (const float*)d_in[7];
    const float* Whh12   = (const float*)d_in[8];
    const float* b12     = (const float*)d_in[9];
    const float* attnW1  = (const float*)d_in[10];
    const float* attnb1  = (const float*)d_in[11];
    const float* attnW2  = (const float*)d_in[12];
    const float* attnb2  = (const float*)d_in[13];
    const float* valW    = (const float*)d_in[14];
    const float* valb    = (const float*)d_in[15];
    const float* weight  = (const float*)d_in[16];
    const float* bias    = (const float*)d_in[17];
    float* out = (float*)d_out;

    float *pre, *seqA, *seqB, *hq, *hk, *P, *sf, *tmpT, *adv;
    cudaGetSymbolAddress((void**)&pre,  g_pre);
    cudaGetSymbolAddress((void**)&seqA, g_seqA);
    cudaGetSymbolAddress((void**)&seqB, g_seqB);
    cudaGetSymbolAddress((void**)&hq,   g_hq);
    cudaGetSymbolAddress((void**)&hk,   g_hk);
    cudaGetSymbolAddress((void**)&P,    g_P);
    cudaGetSymbolAddress((void**)&sf,   g_sf);
    cudaGetSymbolAddress((void**)&tmpT, g_tmpT);
    cudaGetSymbolAddress((void**)&adv,  g_adv);

    const int rec_smem = (48 * 768 + 4 * 768) * 4;
    cudaFuncSetAttribute(rec_kernel, cudaFuncAttributeMaxDynamicSharedMemorySize, rec_smem);

    // layer 0
    tf32gemm_abT<<<dim3(48, 8), 256>>>(states, HB, Wih0, HB, b0, pre, N2, HB);
    rec_kernel<<<RECB, RECT, rec_smem>>>(pre, Whh0, seqA, 256, 0);
    // layer 1
    tf32gemm_abT<<<dim3(48, 8), 256>>>(seqA, D2, Wih12, D2, b12, pre, N2, D2);
    rec_kernel<<<RECB, RECT, rec_smem>>>(pre, Whh12, seqB, 256, 0);
    // layer 2 (tanh fused into output store)
    tf32gemm_abT<<<dim3(48, 8), 256>>>(seqB, D2, Wih12 + (size_t)2 * 3072 * D2, D2,
                                       b12 + 6144, pre, N2, D2);
    rec_kernel<<<RECB, RECT, rec_smem>>>(pre, Whh12 + (size_t)2 * 3072 * HB, seqA, 256, 1);
    // attention projections
    tf32gemm_abT<<<dim3(6, 2), 256>>>(actions, HB, attnW1, 2304, attnb1, hq, HB, HB);
    tf32gemm_abT<<<dim3(6, 8), 256>>>(seqA, D2, attnW1 + HB, 2304, nullptr, hk, HB, D2);
    // scores + softmax
    scores_kernel<<<256, 256>>>(hq, hk, attnW2, attnb2, amask, smask, P);
    // states_feat = P @ out  (batched per b)
    gemm_ab64<<<dim3(24, 1, 4), 256>>>(P, 256, (size_t)64 * 256,
                                       seqA, D2, (size_t)256 * D2,
                                       sf, D2, (size_t)64 * D2, 256);
    // tmpT = sf @ weight^T
    tf32gemm_abT<<<dim3(18, 2), 256>>>(sf, D2, weight, D2, nullptr, tmpT, 2304, D2);
    // adv + final
    adv_kernel<<<256, 256>>>(tmpT, actions, bias, adv);
    final_kernel<<<4, 256>>>(sf, adv, valW, valb, amask, out);
}

// round 6
// speedup vs baseline: 1.4372x; 1.1698x over previous
#include <cuda_runtime.h>
#include <cstdint>

#define HB 768
#define N2 6144
#define D2 1536
#define RECB 128
#define RECT 384
#define SENT 0x7FC00001u

// ----------------------------- scratch (device globals; allocation-free) ----
__device__ float g_pre [1024 * N2];
__device__ float g_hseq[1024 * D2];   // raw-h sequence: comm + layer output
__device__ float g_seqA[1024 * D2];   // tanh(h) of layer 2
__device__ float g_hq  [256 * HB];
__device__ float g_hk  [1024 * HB];
__device__ float g_P   [256 * 256];
__device__ float g_sf  [256 * D2];
__device__ float g_tmpT[256 * 2304];
__device__ float g_adv [256 * 3];

// ---------------------------------------------------------------------------
// TF32 tensor-core GEMM 128x128x16: C = A @ B^T (+bias).
// ---------------------------------------------------------------------------
__device__ __forceinline__ uint32_t f2tf32(float f)
{
    uint32_t u;
    asm("cvt.rna.tf32.f32 %0, %1;" : "=r"(u) : "f"(f));
    return u;
}
__device__ __forceinline__ void mma_tf32(float* c, const uint32_t* a,
                                         uint32_t b0, uint32_t b1)
{
    asm volatile(
        "mma.sync.aligned.m16n8k8.row.col.f32.tf32.tf32.f32 "
        "{%0,%1,%2,%3}, {%4,%5,%6,%7}, {%8,%9}, {%0,%1,%2,%3};\n"
        : "+f"(c[0]), "+f"(c[1]), "+f"(c[2]), "+f"(c[3])
        : "r"(a[0]), "r"(a[1]), "r"(a[2]), "r"(a[3]), "r"(b0), "r"(b1));
}

__global__ __launch_bounds__(256, 2)
void tf32gemm_abT(const float* __restrict__ A, int lda,
                  const float* __restrict__ B, int ldb,
                  const float* __restrict__ bias,
                  float* __restrict__ C, int ldc, int K)
{
    __shared__ uint32_t As[16][136];
    __shared__ uint32_t Bs[16][136];
    const int tid = threadIdx.x;
    const int m0 = blockIdx.y * 128, n0 = blockIdx.x * 128;
    const int warp = tid >> 5, lane = tid & 31;
    const int wm = warp >> 1, wn = warp & 1;
    const int gid = lane >> 2, tig = lane & 3;
    const int lrow = tid >> 2, lk = (tid & 3) * 4;
    const int sxor = ((lk >> 2) & 3) << 3;

    float c[2][8][4];
#pragma unroll
    for (int mt = 0; mt < 2; mt++)
#pragma unroll
        for (int nt = 0; nt < 8; nt++)
#pragma unroll
            for (int q = 0; q < 4; q++) c[mt][nt][q] = 0.f;

    const float* Ap0 = A + (size_t)(m0 + lrow) * lda + lk;
    const float* Ap1 = A + (size_t)(m0 + 64 + lrow) * lda + lk;
    const float* Bp0 = B + (size_t)(n0 + lrow) * ldb + lk;
    const float* Bp1 = B + (size_t)(n0 + 64 + lrow) * ldb + lk;

    for (int k0 = 0; k0 < K; k0 += 16) {
        float4 a0 = *(const float4*)(Ap0 + k0);
        float4 a1 = *(const float4*)(Ap1 + k0);
        float4 b0 = *(const float4*)(Bp0 + k0);
        float4 b1 = *(const float4*)(Bp1 + k0);
        __syncthreads();
        {
            const int c0a = lrow ^ sxor, c1a = (64 + lrow) ^ sxor;
            As[lk+0][c0a] = f2tf32(a0.x); As[lk+1][c0a] = f2tf32(a0.y);
            As[lk+2][c0a] = f2tf32(a0.z); As[lk+3][c0a] = f2tf32(a0.w);
            As[lk+0][c1a] = f2tf32(a1.x); As[lk+1][c1a] = f2tf32(a1.y);
            As[lk+2][c1a] = f2tf32(a1.z); As[lk+3][c1a] = f2tf32(a1.w);
            Bs[lk+0][c0a] = f2tf32(b0.x); Bs[lk+1][c0a] = f2tf32(b0.y);
            Bs[lk+2][c0a] = f2tf32(b0.z); Bs[lk+3][c0a] = f2tf32(b0.w);
            Bs[lk+0][c1a] = f2tf32(b1.x); Bs[lk+1][c1a] = f2tf32(b1.y);
            Bs[lk+2][c1a] = f2tf32(b1.z); Bs[lk+3][c1a] = f2tf32(b1.w);
        }
        __syncthreads();
#pragma unroll
        for (int ks = 0; ks < 2; ks++) {
            const int r0 = ks * 8 + tig;
            const int r1 = ks * 8 + 4 + tig;
            const int x0 = ((r0 >> 2) & 3) << 3;
            const int x1 = ((r1 >> 2) & 3) << 3;
            uint32_t af[2][4];
#pragma unroll
            for (int mt = 0; mt < 2; mt++) {
                const int mb = wm * 32 + mt * 16;
                af[mt][0] = As[r0][(mb + gid) ^ x0];
                af[mt][1] = As[r0][(mb + 8 + gid) ^ x0];
                af[mt][2] = As[r1][(mb + gid) ^ x1];
                af[mt][3] = As[r1][(mb + 8 + gid) ^ x1];
            }
#pragma unroll
            for (int nt = 0; nt < 8; nt++) {
                const int nb = wn * 64 + nt * 8;
                uint32_t bf0 = Bs[r0][(nb + gid) ^ x0];
                uint32_t bf1 = Bs[r1][(nb + gid) ^ x1];
                mma_tf32(c[0][nt], af[0], bf0, bf1);
                mma_tf32(c[1][nt], af[1], bf0, bf1);
            }
        }
    }
#pragma unroll
    for (int mt = 0; mt < 2; mt++) {
        const int row = m0 + wm * 32 + mt * 16 + gid;
#pragma unroll
        for (int nt = 0; nt < 8; nt++) {
            const int col = n0 + wn * 64 + nt * 8 + tig * 2;
            float bv0 = bias ? bias[col] : 0.f;
            float bv1 = bias ? bias[col + 1] : 0.f;
            float2 v0 = make_float2(c[mt][nt][0] + bv0, c[mt][nt][1] + bv1);
            float2 v1 = make_float2(c[mt][nt][2] + bv0, c[mt][nt][3] + bv1);
            *(float2*)&C[(size_t)row * ldc + col] = v0;
            *(float2*)&C[(size_t)(row + 8) * ldc + col] = v1;
        }
    }
}

// ---------------------------------------------------------------------------
// Batched GEMM 64x64x16: C = A @ B (for P @ out).
// ---------------------------------------------------------------------------
__global__ __launch_bounds__(256)
void gemm_ab64(const float* __restrict__ Ab, int lda, size_t strA,
               const float* __restrict__ Bb, int ldb, size_t strB,
               float* __restrict__ Cb, int ldc, size_t strC, int K)
{
    const float* A = Ab + strA * blockIdx.z;
    const float* B = Bb + strB * blockIdx.z;
    float* C = Cb + strC * blockIdx.z;
    __shared__ float As[16][68];
    __shared__ float Bs[16][68];
    const int tid = threadIdx.x;
    const int m0 = blockIdx.y * 64, n0 = blockIdx.x * 64;
    const int tx = tid & 15, ty = tid >> 4;
    const int lrow = tid >> 2, lk = (tid & 3) * 4;
    const int bkk = tid >> 4, bnq = (tid & 15) * 4;

    float acc[4][4];
#pragma unroll
    for (int i = 0; i < 4; i++)
#pragma unroll
        for (int j = 0; j < 4; j++) acc[i][j] = 0.f;

    for (int k0 = 0; k0 < K; k0 += 16) {
        float4 a0 = *(const float4*)&A[(size_t)(m0 + lrow) * lda + k0 + lk];
        float4 b0 = *(const float4*)&B[(size_t)(k0 + bkk) * ldb + n0 + bnq];
        __syncthreads();
        As[lk+0][lrow]=a0.x; As[lk+1][lrow]=a0.y; As[lk+2][lrow]=a0.z; As[lk+3][lrow]=a0.w;
        *(float4*)&Bs[bkk][bnq] = b0;
        __syncthreads();
#pragma unroll
        for (int kk = 0; kk < 16; kk++) {
            float ar[4], br[4];
            *(float4*)&ar[0] = *(const float4*)&As[kk][ty * 4];
            *(float4*)&br[0] = *(const float4*)&Bs[kk][tx * 4];
#pragma unroll
            for (int i = 0; i < 4; i++)
#pragma unroll
                for (int j = 0; j < 4; j++) acc[i][j] += ar[i] * br[j];
        }
    }
#pragma unroll
    for (int i = 0; i < 4; i++) {
        float4 v = make_float4(acc[i][0], acc[i][1], acc[i][2], acc[i][3]);
        *(float4*)&C[(size_t)(m0 + ty * 4 + i) * ldc + n0 + tx * 4] = v;
    }
}

// ---------------------------------------------------------------------------
// Poison hseq with the NaN sentinel (consumers poll for non-sentinel data).
// ---------------------------------------------------------------------------
__global__ void poison_kernel(float4* __restrict__ p, int n4)
{
    int i = blockIdx.x * blockDim.x + threadIdx.x;
    float s = __uint_as_float(SENT);
    if (i < n4) p[i] = make_float4(s, s, s, s);
}

// ---------------------------------------------------------------------------
// Persistent BiLSTM recurrence v3 — barrier-free dataflow.
// 128 CTAs x 384 thr; CTA: dir = bx>>6, cells [c0,c0+12); warp rg = cell
// c0+rg (all 4 gates); lanes split k. h[t] lives in hseq (the layer output);
// consumers poll it directly with ld.global.cg until non-sentinel.
// c-state in registers of lanes 0..3 (lane = batch).
// ---------------------------------------------------------------------------
__device__ __forceinline__ float sigf(float x) { return 1.f / (1.f + expf(-x)); }

__device__ __forceinline__ float4 ldcg4(const float* p)
{
    float4 v;
    asm volatile("ld.global.cg.v4.f32 {%0,%1,%2,%3}, [%4];"
                 : "=f"(v.x), "=f"(v.y), "=f"(v.z), "=f"(v.w) : "l"(p));
    return v;
}
__device__ __forceinline__ bool valid4(float4 v)
{
    return (__float_as_uint(v.x) != SENT) & (__float_as_uint(v.y) != SENT) &
           (__float_as_uint(v.z) != SENT) & (__float_as_uint(v.w) != SENT);
}

__global__ __launch_bounds__(RECT, 1)
void rec_kernel(const float* __restrict__ pre,   // [1024][6144]
                const float* __restrict__ whh,   // [2][3072][768]
                float* __restrict__ hseq,        // [1024][1536] raw h (poisoned)
                float* __restrict__ out2,        // tanh(h) when do_tanh
                int T, int do_tanh)
{
    extern __shared__ float sm[];
    float* sW = sm;               // [48][768]
    float* sh = sW + 48 * 768;    // [4][768]

    const int tid = threadIdx.x;
    const int bx  = blockIdx.x;
    const int dir = bx >> 6;
    const int c0  = (bx & 63) * 12;
    const int rg  = tid >> 5, ks = tid & 31;

    // stage Whh slice: row r=g*12+jj <- whh[dir][g*768+c0+jj][:]
    for (int idx = tid; idx < 9216; idx += RECT) {
        int r = idx / 192, kc = (idx - r * 192) * 4;
        int g = r / 12, jj = r - g * 12;
        *(float4*)&sW[r * 768 + kc] =
            *(const float4*)&whh[((size_t)dir * 3072 + g * 768 + c0 + jj) * 768 + kc];
    }

    // poll assignment: 768 float4s of h (4 batches x 192), 2 per thread
    const int f0 = tid, f1 = tid + RECT;
    const int pb0 = f0 / 192, pj0 = (f0 - pb0 * 192) * 4;
    const int pb1 = f1 / 192, pj1 = (f1 - pb1 * 192) * 4;

    float creg = 0.f;
    for (int step = 0; step < T; step++) {
        const int t  = (dir == 0) ? step : (T - 1 - step);
        const int tp = (dir == 0) ? t - 1 : t + 1;   // previous h row

        // prefetch pre-activations (lane ks<4 = batch)
        float pg0 = 0.f, pg1 = 0.f, pg2 = 0.f, pg3 = 0.f;
        if (ks < 4) {
            const float* pp = pre + (size_t)(ks * 256 + t) * N2 + dir * 3072 + c0 + rg;
            pg0 = __ldg(pp + 0 * 768);
            pg1 = __ldg(pp + 1 * 768);
            pg2 = __ldg(pp + 2 * 768);
            pg3 = __ldg(pp + 3 * 768);
        }

        if (step == 0) {
            *(float4*)&sh[pb0 * 768 + pj0] = make_float4(0.f, 0.f, 0.f, 0.f);
            *(float4*)&sh[pb1 * 768 + pj1] = make_float4(0.f, 0.f, 0.f, 0.f);
        } else {
            const float* p0 = hseq + (size_t)(pb0 * 256 + tp) * D2 + dir * HB + pj0;
            const float* p1 = hseq + (size_t)(pb1 * 256 + tp) * D2 + dir * HB + pj1;
            float4 v0, v1;
            bool d0 = false, d1 = false;
            do {
                if (!d0) { v0 = ldcg4(p0); d0 = valid4(v0); }
                if (!d1) { v1 = ldcg4(p1); d1 = valid4(v1); }
            } while (!(d0 && d1));
            *(float4*)&sh[pb0 * 768 + pj0] = v0;
            *(float4*)&sh[pb1 * 768 + pj1] = v1;
        }
        __syncthreads();

        // warp rg: gates g=0..3 of cell c0+rg, batches 0..3; k over lanes
        float acc[4][4];
#pragma unroll
        for (int g = 0; g < 4; g++)
#pragma unroll
            for (int b = 0; b < 4; b++) acc[g][b] = 0.f;
        const float* w0p = sW + (0 * 12 + rg) * 768;
        const float* w1p = sW + (1 * 12 + rg) * 768;
        const float* w2p = sW + (2 * 12 + rg) * 768;
        const float* w3p = sW + (3 * 12 + rg) * 768;
#pragma unroll
        for (int it = 0; it < 6; it++) {
            int ko = it * 128 + ks * 4;
            float4 w0 = *(const float4*)(w0p + ko);
            float4 w1 = *(const float4*)(w1p + ko);
            float4 w2 = *(const float4*)(w2p + ko);
            float4 w3 = *(const float4*)(w3p + ko);
            float4 h0 = *(const float4*)(sh + 0 * 768 + ko);
            float4 h1 = *(const float4*)(sh + 1 * 768 + ko);
            float4 h2 = *(const float4*)(sh + 2 * 768 + ko);
            float4 h3 = *(const float4*)(sh + 3 * 768 + ko);
#define FMA16(G, W) \
            acc[G][0] += W.x*h0.x + W.y*h0.y + W.z*h0.z + W.w*h0.w; \
            acc[G][1] += W.x*h1.x + W.y*h1.y + W.z*h1.z + W.w*h1.w; \
            acc[G][2] += W.x*h2.x + W.y*h2.y + W.z*h2.z + W.w*h2.w; \
            acc[G][3] += W.x*h3.x + W.y*h3.y + W.z*h3.z + W.w*h3.w;
            FMA16(0, w0) FMA16(1, w1) FMA16(2, w2) FMA16(3, w3)
#undef FMA16
        }
#pragma unroll
        for (int o = 16; o; o >>= 1)
#pragma unroll
            for (int g = 0; g < 4; g++)
#pragma unroll
                for (int b = 0; b < 4; b++)
                    acc[g][b] += __shfl_xor_sync(0xffffffffu, acc[g][b], o);

        if (ks < 4) {
            const int b = ks;
            float xi = acc[0][b] + pg0;
            float xf = acc[1][b] + pg1;
            float xg = acc[2][b] + pg2;
            float xo = acc[3][b] + pg3;
            creg = sigf(xf) * creg + sigf(xi) * tanhf(xg);
            float h = sigf(xo) * tanhf(creg);
            const size_t oi = (size_t)(b * 256 + t) * D2 + dir * HB + c0 + rg;
            __stcg(&hseq[oi], h);                    // data IS the flag
            if (do_tanh) out2[oi] = tanhf(h);
        }
        __syncthreads();   // protect sh from next iteration's poll writes
    }
}

// ---------------------------------------------------------------------------
__device__ __forceinline__ float blockReduceSum(float v, float* sr)
{
    __syncthreads();
#pragma unroll
    for (int o = 16; o; o >>= 1) v += __shfl_xor_sync(0xffffffffu, v, o);
    int lane = threadIdx.x & 31, w = threadIdx.x >> 5;
    if (lane == 0) sr[w] = v;
    __syncthreads();
    if (w == 0) {
        int nw = (blockDim.x + 31) >> 5;
        v = (lane < nw) ? sr[lane] : 0.f;
#pragma unroll
        for (int o = 16; o; o >>= 1) v += __shfl_xor_sync(0xffffffffu, v, o);
        if (lane == 0) sr[0] = v;
    }
    __syncthreads();
    return sr[0];
}

// scores + softmax: block per (b,q); thread = k.
__global__ __launch_bounds__(256)
void scores_kernel(const float* __restrict__ hq, const float* __restrict__ hk,
                   const float* __restrict__ w2, const float* __restrict__ b2p,
                   const float* __restrict__ am, const float* __restrict__ smk,
                   float* __restrict__ P)
{
    __shared__ float shq[768], sw2[768], shk[256 * 33], sr[32];
    const int tid = threadIdx.x, bq = blockIdx.x;
    const int b = bq >> 6, q = bq & 63;
    for (int i = tid; i < 768; i += 256) { shq[i] = hq[bq * 768 + i]; sw2[i] = w2[i]; }
    float acc = 0.f;
    for (int e0 = 0; e0 < 768; e0 += 32) {
        __syncthreads();
        for (int idx = tid; idx < 256 * 32; idx += 256) {
            int k = idx >> 5, e = idx & 31;
            shk[k * 33 + e] = hk[(size_t)((b << 8) + k) * 768 + e0 + e];
        }
        __syncthreads();
#pragma unroll 8
        for (int e = 0; e < 32; e++) {
            float v = shq[e0 + e] + shk[tid * 33 + e];
            acc += fmaxf(v, 0.f) * sw2[e0 + e];
        }
    }
    float score = acc + b2p[0];
    float m = am[b * 64 + q] * smk[b * 256 + tid];
    float a = (m == 0.f) ? 0.f : expf(score);
    float s = blockReduceSum(a, sr);
    P[bq * 256 + tid] = a / fmaxf(s, 2e-15f);
}

__global__ __launch_bounds__(256)
void adv_kernel(const float* __restrict__ tmpT, const float* __restrict__ act,
                const float* __restrict__ bias, float* __restrict__ adv)
{
    __shared__ float sa[768], sr[32];
    const int tid = threadIdx.x, bq = blockIdx.x;
    for (int i = tid; i < 768; i += 256) sa[i] = act[(size_t)bq * 768 + i];
    for (int l = 0; l < 3; l++) {
        float acc = 0.f;
        for (int h = tid; h < 768; h += 256)
            acc += tmpT[(size_t)bq * 2304 + l * 768 + h] * sa[h];
        float s = blockReduceSum(acc, sr);
        if (tid == 0) adv[bq * 3 + l] = s + bias[l];
    }
}

__global__ __launch_bounds__(256)
void final_kernel(const float* __restrict__ sf, const float* __restrict__ adv,
                  const float* __restrict__ valW, const float* __restrict__ valbp,
                  const float* __restrict__ am, float* __restrict__ out)
{
    __shared__ float sr[32];
    const int tid = threadIdx.x, b = blockIdx.x;
    float accv = 0.f;
    for (int d = tid; d < D2; d += 256) {
        float s = 0.f;
        for (int q = 0; q < 64; q++) s += sf[(size_t)(b * 64 + q) * D2 + d];
        accv += s * valW[d];
    }
    accv = blockReduceSum(accv, sr);
    float nv = (tid < 64) ? am[b * 64 + tid] : 0.f;
    nv = blockReduceSum(nv, sr);
    float asum = 0.f;
    for (int i = tid; i < 192; i += 256) asum += adv[b * 192 + i];
    asum = blockReduceSum(asum, sr);
    float val = accv / nv + valbp[0];
    float mean = asum / 192.f;
    for (int i = tid; i < 192; i += 256)
        out[b * 192 + i] = val + adv[b * 192 + i] - mean;
}

// ---------------------------------------------------------------------------
extern "C" void kernel_launch(void* const* d_in, const int* in_sizes, int n_in,
                              void* d_out, int out_size)
{
    const float* states  = (const float*)d_in[0];
    const float* smask   = (const float*)d_in[1];
    const float* actions = (const float*)d_in[2];
    const float* amask   = (const float*)d_in[3];
    const float* Wih0    = (const float*)d_in[4];
    const float* Whh0    = (const float*)d_in[5];
    const float* b0      = (const float*)d_in[6];
    const float* Wih12   = (const float*)d_in[7];
    const float* Whh12   = (const float*)d_in[8];
    const float* b12     = (const float*)d_in[9];
    const float* attnW1  = (const float*)d_in[10];
    const float* attnb1  = (const float*)d_in[11];
    const float* attnW2  = (const float*)d_in[12];
    const float* attnb2  = (const float*)d_in[13];
    const float* valW    = (const float*)d_in[14];
    const float* valb    = (const float*)d_in[15];
    const float* weight  = (const float*)d_in[16];
    const float* bias    = (const float*)d_in[17];
    float* out = (float*)d_out;

    float *pre, *hseq, *seqA, *hq, *hk, *P, *sf, *tmpT, *adv;
    cudaGetSymbolAddress((void**)&pre,  g_pre);
    cudaGetSymbolAddress((void**)&hseq, g_hseq);
    cudaGetSymbolAddress((void**)&seqA, g_seqA);
    cudaGetSymbolAddress((void**)&hq,   g_hq);
    cudaGetSymbolAddress((void**)&hk,   g_hk);
    cudaGetSymbolAddress((void**)&P,    g_P);
    cudaGetSymbolAddress((void**)&sf,   g_sf);
    cudaGetSymbolAddress((void**)&tmpT, g_tmpT);
    cudaGetSymbolAddress((void**)&adv,  g_adv);

    const int rec_smem = (48 * 768 + 4 * 768) * 4;
    cudaFuncSetAttribute(rec_kernel, cudaFuncAttributeMaxDynamicSharedMemorySize, rec_smem);

    const int n4 = 1024 * D2 / 4;

    // layer 0
    poison_kernel<<<(n4 + 255) / 256, 256>>>((float4*)hseq, n4);
    tf32gemm_abT<<<dim3(48, 8), 256>>>(states, HB, Wih0, HB, b0, pre, N2, HB);
    rec_kernel<<<RECB, RECT, rec_smem>>>(pre, Whh0, hseq, nullptr, 256, 0);
    // layer 1
    tf32gemm_abT<<<dim3(48, 8), 256>>>(hseq, D2, Wih12, D2, b12, pre, N2, D2);
    poison_kernel<<<(n4 + 255) / 256, 256>>>((float4*)hseq, n4);
    rec_kernel<<<RECB, RECT, rec_smem>>>(pre, Whh12, hseq, nullptr, 256, 0);
    // layer 2 (raw h -> hseq for dataflow, tanh(h) -> seqA for attention)
    tf32gemm_abT<<<dim3(48, 8), 256>>>(hseq, D2, Wih12 + (size_t)2 * 3072 * D2, D2,
                                       b12 + 6144, pre, N2, D2);
    poison_kernel<<<(n4 + 255) / 256, 256>>>((float4*)hseq, n4);
    rec_kernel<<<RECB, RECT, rec_smem>>>(pre, Whh12 + (size_t)2 * 3072 * HB, hseq, seqA, 256, 1);
    // attention projections
    tf32gemm_abT<<<dim3(6, 2), 256>>>(actions, HB, attnW1, 2304, attnb1, hq, HB, HB);
    tf32gemm_abT<<<dim3(6, 8), 256>>>(seqA, D2, attnW1 + HB, 2304, nullptr, hk, HB, D2);
    // scores + softmax
    scores_kernel<<<256, 256>>>(hq, hk, attnW2, attnb2, amask, smask, P);
    // states_feat = P @ out  (batched per b)
    gemm_ab64<<<dim3(24, 1, 4), 256>>>(P, 256, (size_t)64 * 256,
                                       seqA, D2, (size_t)256 * D2,
                                       sf, D2, (size_t)64 * D2, 256);
    // tmpT = sf @ weight^T
    tf32gemm_abT<<<dim3(18, 2), 256>>>(sf, D2, weight, D2, nullptr, tmpT, 2304, D2);
    // adv + final
    adv_kernel<<<256, 256>>>(tmpT, actions, bias, adv);
    final_kernel<<<4, 256>>>(sf, adv, valW, valb, amask, out);
}